// round 2
// baseline (speedup 1.0000x reference)
#include <cuda_runtime.h>
#include <math.h>

#define BATCH 16
#define CH 512
#define RES 64
#define HW 4096
#define OT 16     // output channels per CTA
#define KC 16     // c-chunk
#define NTHR 256

__device__ float g_s[BATCH * CH];      // conv styles
__device__ float g_s2[BATCH * CH];     // rgb styles (incl. weight_gain)
__device__ float g_dcoef[BATCH * CH];  // demod coefficients
__device__ float g_wsq[CH * CH];       // sum_k conv_w[o,c,k]^2

// packed fp32x2 FMA (ptxas won't emit FFMA2 from C++; PTX fma.rn.f32x2 does)
__device__ __forceinline__ void fma2(float2& d, float2 a, float2 b, float2 c) {
    asm("fma.rn.f32x2 %0, %1, %2, %3;"
        : "=l"(reinterpret_cast<unsigned long long&>(d))
        : "l"(reinterpret_cast<unsigned long long&>(a)),
          "l"(reinterpret_cast<unsigned long long&>(b)),
          "l"(reinterpret_cast<unsigned long long&>(c)));
}

// ---------------- styles ----------------
__global__ void k_style(const float* __restrict__ ws, const float* __restrict__ caw,
                        const float* __restrict__ cab, const float* __restrict__ raw,
                        const float* __restrict__ rab) {
    int widx = blockIdx.x * 8 + (threadIdx.x >> 5);
    int lane = threadIdx.x & 31;
    int b = widx >> 9, c = widx & 511;
    const float* w0 = ws + b * 1024;
    const float* w1 = w0 + 512;
    const float* ca = caw + c * 512;
    const float* ra = raw + c * 512;
    float a1 = 0.f, a2 = 0.f;
    for (int d = lane; d < 512; d += 32) {
        a1 = fmaf(w0[d], ca[d], a1);
        a2 = fmaf(w1[d], ra[d], a2);
    }
    #pragma unroll
    for (int o = 16; o; o >>= 1) {
        a1 += __shfl_xor_sync(0xffffffffu, a1, o);
        a2 += __shfl_xor_sync(0xffffffffu, a2, o);
    }
    if (lane == 0) {
        g_s[b * 512 + c] = a1 + cab[c];
        g_s2[b * 512 + c] = (a2 + rab[c]) * 0.04419417382415922f;
    }
}

// ---------------- wsq ----------------
__global__ void k_wsq(const float* __restrict__ cw) {
    int idx = blockIdx.x * 256 + threadIdx.x;
    const float* p = cw + (size_t)idx * 9;
    float s = 0.f;
    #pragma unroll
    for (int k = 0; k < 9; k++) s = fmaf(p[k], p[k], s);
    g_wsq[idx] = s;
}

// ---------------- dcoef ----------------
__global__ void k_dcoef() {
    int widx = blockIdx.x * 8 + (threadIdx.x >> 5);
    int lane = threadIdx.x & 31;
    int b = widx >> 9, o = widx & 511;
    const float* wq = g_wsq + o * 512;
    const float* sp = g_s + b * 512;
    float a = 0.f;
    for (int c = lane; c < 512; c += 32) {
        float sv = sp[c];
        a = fmaf(wq[c] * sv, sv, a);
    }
    #pragma unroll
    for (int off = 16; off; off >>= 1) a += __shfl_xor_sync(0xffffffffu, a, off);
    if (!lane) g_dcoef[b * 512 + o] = rsqrtf(a + 1e-8f);
}

// ---------------- main fused kernel (FFMA2 version) ----------------
// CTA: one row y, 16 output channels, all 16 batches. 256 threads, 2 CTAs/SM.
__global__ __launch_bounds__(NTHR, 2)
void k_main(const float* __restrict__ cst, const float* __restrict__ cw,
            const float* __restrict__ cb, const float* __restrict__ nzc,
            const float* __restrict__ nzs, float* __restrict__ out) {
    __shared__ float2 sm_w[KC][OT][10];   // taps duplicated (v,v), pad 9->10
    __shared__ float  sm_c[KC][3][72];    // halo-padded const rows
    __shared__ float2 sm_s[KC][16];       // styles duplicated (v,v)

    const int y = blockIdx.x;
    const int obase = blockIdx.y * OT;
    const int tid = threadIdx.x;
    const int ol = tid >> 4;       // 0..15 output channel within tile
    const int pg = tid & 15;
    const int x0 = pg << 2;        // 4 contiguous pixels
    const int og = obase + ol;

    if (tid < KC * 3) {
        sm_c[tid / 3][tid % 3][0] = 0.f;
        sm_c[tid / 3][tid % 3][65] = 0.f;
    }

    float2 accA[16], accB[16];     // accA=(px0,px1) accB=(px2,px3) per batch
    #pragma unroll
    for (int b = 0; b < 16; b++) { accA[b] = make_float2(0.f, 0.f); accB[b] = make_float2(0.f, 0.f); }

    for (int c0 = 0; c0 < CH; c0 += KC) {
        __syncthreads();
        {   // weights: thread = (oo, cc) pair, 256 exactly
            int cc = tid & 15;
            int oo = tid >> 4;
            const float* gp = cw + ((size_t)(obase + oo) * CH + (c0 + cc)) * 9;
            #pragma unroll
            for (int k = 0; k < 9; k++) { float v = gp[k]; sm_w[cc][oo][k] = make_float2(v, v); }
        }
        // const rows y-1..y+1 for KC channels: 3072 elems over 256 threads
        #pragma unroll
        for (int it = 0; it < 12; it++) {
            int i = tid + it * NTHR;
            int cc = i / 192;
            int rem = i - cc * 192;
            int r = rem >> 6;
            int col = rem & 63;
            int yy = y + r - 1;
            float v = 0.f;
            if ((unsigned)yy < 64u) v = cst[(size_t)(c0 + cc) * HW + yy * 64 + col];
            sm_c[cc][r][col + 1] = v;
        }
        {   // styles duplicated
            int cc = tid >> 4, b = tid & 15;
            float v = g_s[b * CH + c0 + cc];
            sm_s[cc][b] = make_float2(v, v);
        }
        __syncthreads();

        #pragma unroll 4
        for (int cc = 0; cc < KC; cc++) {
            const float2* wp = &sm_w[cc][ol][0];
            float4 q0 = *(const float4*)&wp[0];   // w0,w1 dup
            float4 q1 = *(const float4*)&wp[2];   // w2,w3
            float4 q2 = *(const float4*)&wp[4];   // w4,w5
            float4 q3 = *(const float4*)&wp[6];   // w6,w7
            float2 pw8 = wp[8];

            float2 zA = make_float2(0.f, 0.f), zB = make_float2(0.f, 0.f);
            {   // row y-1: taps w0,w1,w2
                float4 a = *(const float4*)&sm_c[cc][0][x0];
                float2 e = *(const float2*)&sm_c[cc][0][x0 + 4];
                float2 pa = make_float2(q0.x, q0.y), pb = make_float2(q0.z, q0.w), pc = make_float2(q1.x, q1.y);
                float2 p0 = make_float2(a.x, a.y), p2 = make_float2(a.z, a.w), p4 = e;
                float2 m1 = make_float2(a.y, a.z), m3 = make_float2(a.w, e.x);
                fma2(zA, pa, p0, zA); fma2(zA, pb, m1, zA); fma2(zA, pc, p2, zA);
                fma2(zB, pa, p2, zB); fma2(zB, pb, m3, zB); fma2(zB, pc, p4, zB);
            }
            {   // row y: taps w3,w4,w5
                float4 a = *(const float4*)&sm_c[cc][1][x0];
                float2 e = *(const float2*)&sm_c[cc][1][x0 + 4];
                float2 pa = make_float2(q1.z, q1.w), pb = make_float2(q2.x, q2.y), pc = make_float2(q2.z, q2.w);
                float2 p0 = make_float2(a.x, a.y), p2 = make_float2(a.z, a.w), p4 = e;
                float2 m1 = make_float2(a.y, a.z), m3 = make_float2(a.w, e.x);
                fma2(zA, pa, p0, zA); fma2(zA, pb, m1, zA); fma2(zA, pc, p2, zA);
                fma2(zB, pa, p2, zB); fma2(zB, pb, m3, zB); fma2(zB, pc, p4, zB);
            }
            {   // row y+1: taps w6,w7,w8
                float4 a = *(const float4*)&sm_c[cc][2][x0];
                float2 e = *(const float2*)&sm_c[cc][2][x0 + 4];
                float2 pa = make_float2(q3.x, q3.y), pb = make_float2(q3.z, q3.w), pc = pw8;
                float2 p0 = make_float2(a.x, a.y), p2 = make_float2(a.z, a.w), p4 = e;
                float2 m1 = make_float2(a.y, a.z), m3 = make_float2(a.w, e.x);
                fma2(zA, pa, p0, zA); fma2(zA, pb, m1, zA); fma2(zA, pc, p2, zA);
                fma2(zB, pa, p2, zB); fma2(zB, pb, m3, zB); fma2(zB, pc, p4, zB);
            }
            // mix: acc[b] += s[b] * z  (16 batches, packed)
            #pragma unroll
            for (int i = 0; i < 8; i++) {
                float4 t = *(const float4*)&sm_s[cc][2 * i];
                float2 s0 = make_float2(t.x, t.y), s1 = make_float2(t.z, t.w);
                fma2(accA[2 * i],     s0, zA, accA[2 * i]);
                fma2(accB[2 * i],     s0, zB, accB[2 * i]);
                fma2(accA[2 * i + 1], s1, zA, accA[2 * i + 1]);
                fma2(accB[2 * i + 1], s1, zB, accB[2 * i + 1]);
            }
        }
    }

    // epilogue
    float nsv = nzs[0];
    float bo = cb[og];
    float nv[4];
    #pragma unroll
    for (int j = 0; j < 4; j++) nv[j] = fmaf(nzc[y * 64 + x0 + j], nsv, bo);
    const float gain = 1.4142135623730951f;
    size_t pxoff = (size_t)y * 64 + x0;
    #pragma unroll
    for (int b = 0; b < 16; b++) {
        float dc = g_dcoef[b * CH + og];
        float4 v;
        float t;
        t = fmaf(accA[b].x, dc, nv[0]); v.x = (t > 0.f ? t : 0.2f * t) * gain;
        t = fmaf(accA[b].y, dc, nv[1]); v.y = (t > 0.f ? t : 0.2f * t) * gain;
        t = fmaf(accB[b].x, dc, nv[2]); v.z = (t > 0.f ? t : 0.2f * t) * gain;
        t = fmaf(accB[b].y, dc, nv[3]); v.w = (t > 0.f ? t : 0.2f * t) * gain;
        *(float4*)(out + ((size_t)(b * CH + og)) * HW + pxoff) = v;
    }
}

// ---------------- ToRGB ----------------
__global__ void k_rgb(const float* __restrict__ x, const float* __restrict__ rgbw,
                      const float* __restrict__ rgbb, float* __restrict__ img) {
    __shared__ float rw[3][512];
    int b = blockIdx.y;
    int px = blockIdx.x * 256 + threadIdx.x;
    for (int i = threadIdx.x; i < 1536; i += 256) {
        int ch = i >> 9, o = i & 511;
        rw[ch][o] = rgbw[ch * 512 + o] * g_s2[b * 512 + o];
    }
    __syncthreads();
    const float* xp = x + (size_t)b * CH * HW + px;
    float a0 = 0.f, a1 = 0.f, a2 = 0.f;
    #pragma unroll 8
    for (int o = 0; o < 512; o++) {
        float xv = xp[(size_t)o * HW];
        a0 = fmaf(rw[0][o], xv, a0);
        a1 = fmaf(rw[1][o], xv, a1);
        a2 = fmaf(rw[2][o], xv, a2);
    }
    size_t base = (size_t)b * 3 * HW + px;
    img[base] = a0 + rgbb[0];
    img[base + HW] = a1 + rgbb[1];
    img[base + 2 * HW] = a2 + rgbb[2];
}

extern "C" void kernel_launch(void* const* d_in, const int* in_sizes, int n_in,
                              void* d_out, int out_size) {
    const float* ws   = (const float*)d_in[0];
    const float* cst  = (const float*)d_in[1];
    const float* cw   = (const float*)d_in[2];
    const float* cb   = (const float*)d_in[3];
    const float* caw  = (const float*)d_in[4];
    const float* cab  = (const float*)d_in[5];
    const float* nzc  = (const float*)d_in[6];
    const float* nzs  = (const float*)d_in[7];
    const float* rgbw = (const float*)d_in[8];
    const float* rgbb = (const float*)d_in[9];
    const float* raw  = (const float*)d_in[10];
    const float* rab  = (const float*)d_in[11];
    float* out = (float*)d_out;

    k_style<<<1024, 256>>>(ws, caw, cab, raw, rab);
    k_wsq<<<1024, 256>>>(cw);
    k_dcoef<<<1024, 256>>>();
    dim3 g(64, 32);   // 64 rows x 32 o-tiles of 16
    k_main<<<g, NTHR>>>(cst, cw, cb, nzc, nzs, out);
    k_rgb<<<dim3(16, 16), 256>>>(out, rgbw, rgbb, out + (size_t)BATCH * CH * HW);
}

// round 3
// speedup vs baseline: 1.1190x; 1.1190x over previous
#include <cuda_runtime.h>
#include <math.h>

#define BATCH 16
#define CH 512
#define RES 64
#define HW 4096
#define OT 16     // output channels per CTA
#define KC 16     // c-chunk
#define NTHR 256

__device__ float g_s[BATCH * CH];      // conv styles
__device__ float g_s2[BATCH * CH];     // rgb styles (incl. weight_gain)
__device__ float g_dcoef[BATCH * CH];  // demod coefficients
__device__ float g_wsq[CH * CH];       // sum_k conv_w[o,c,k]^2

// packed fp32x2 FMA
__device__ __forceinline__ void fma2(float2& d, float2 a, float2 b, float2 c) {
    asm("fma.rn.f32x2 %0, %1, %2, %3;"
        : "=l"(reinterpret_cast<unsigned long long&>(d))
        : "l"(reinterpret_cast<unsigned long long&>(a)),
          "l"(reinterpret_cast<unsigned long long&>(b)),
          "l"(reinterpret_cast<unsigned long long&>(c)));
}

// ---------------- styles ----------------
__global__ void k_style(const float* __restrict__ ws, const float* __restrict__ caw,
                        const float* __restrict__ cab, const float* __restrict__ raw,
                        const float* __restrict__ rab) {
    int widx = blockIdx.x * 8 + (threadIdx.x >> 5);
    int lane = threadIdx.x & 31;
    int b = widx >> 9, c = widx & 511;
    const float* w0 = ws + b * 1024;
    const float* w1 = w0 + 512;
    const float* ca = caw + c * 512;
    const float* ra = raw + c * 512;
    float a1 = 0.f, a2 = 0.f;
    for (int d = lane; d < 512; d += 32) {
        a1 = fmaf(w0[d], ca[d], a1);
        a2 = fmaf(w1[d], ra[d], a2);
    }
    #pragma unroll
    for (int o = 16; o; o >>= 1) {
        a1 += __shfl_xor_sync(0xffffffffu, a1, o);
        a2 += __shfl_xor_sync(0xffffffffu, a2, o);
    }
    if (lane == 0) {
        g_s[b * 512 + c] = a1 + cab[c];
        g_s2[b * 512 + c] = (a2 + rab[c]) * 0.04419417382415922f;
    }
}

// ---------------- wsq ----------------
__global__ void k_wsq(const float* __restrict__ cw) {
    int idx = blockIdx.x * 256 + threadIdx.x;
    const float* p = cw + (size_t)idx * 9;
    float s = 0.f;
    #pragma unroll
    for (int k = 0; k < 9; k++) s = fmaf(p[k], p[k], s);
    g_wsq[idx] = s;
}

// ---------------- dcoef ----------------
__global__ void k_dcoef() {
    int widx = blockIdx.x * 8 + (threadIdx.x >> 5);
    int lane = threadIdx.x & 31;
    int b = widx >> 9, o = widx & 511;
    const float* wq = g_wsq + o * 512;
    const float* sp = g_s + b * 512;
    float a = 0.f;
    for (int c = lane; c < 512; c += 32) {
        float sv = sp[c];
        a = fmaf(wq[c] * sv, sv, a);
    }
    #pragma unroll
    for (int off = 16; off; off >>= 1) a += __shfl_xor_sync(0xffffffffu, a, off);
    if (!lane) g_dcoef[b * 512 + o] = rsqrtf(a + 1e-8f);
}

// ---------------- main fused kernel ----------------
// CTA: one row y, 16 output channels, all 16 batches. 256 threads, 2 CTAs/SM.
// Mix is batch-pair packed: acc2[i][j] (+)= (s[2i],s[2i+1]) * (z_j,z_j)
__global__ __launch_bounds__(NTHR, 2)
void k_main(const float* __restrict__ cst, const float* __restrict__ cw,
            const float* __restrict__ cb, const float* __restrict__ nzc,
            const float* __restrict__ nzs, float* __restrict__ out) {
    __shared__ float2 sm_w[KC][OT][10];   // taps duplicated (v,v)
    __shared__ float  sm_c[KC][3][72];    // halo-padded const rows
    __shared__ float  sm_s[KC][16];       // styles scalar

    const int y = blockIdx.x;
    const int obase = blockIdx.y * OT;
    const int tid = threadIdx.x;
    const int ol = tid >> 4;       // 0..15 output channel within tile
    const int pg = tid & 15;
    const int x0 = pg << 2;        // 4 contiguous pixels
    const int og = obase + ol;

    if (tid < KC * 3) {
        sm_c[tid / 3][tid % 3][0] = 0.f;
        sm_c[tid / 3][tid % 3][65] = 0.f;
    }

    float2 acc2[8][4];             // [batch-pair][pixel]
    #pragma unroll
    for (int i = 0; i < 8; i++)
        #pragma unroll
        for (int j = 0; j < 4; j++) acc2[i][j] = make_float2(0.f, 0.f);

    for (int c0 = 0; c0 < CH; c0 += KC) {
        __syncthreads();
        {   // weights duplicated: thread = (oo, cc)
            int cc = tid & 15;
            int oo = tid >> 4;
            const float* gp = cw + ((size_t)(obase + oo) * CH + (c0 + cc)) * 9;
            #pragma unroll
            for (int k = 0; k < 9; k++) { float v = gp[k]; sm_w[cc][oo][k] = make_float2(v, v); }
        }
        // const rows y-1..y+1 for KC channels
        #pragma unroll
        for (int it = 0; it < 12; it++) {
            int i = tid + it * NTHR;
            int cc = i / 192;
            int rem = i - cc * 192;
            int r = rem >> 6;
            int col = rem & 63;
            int yy = y + r - 1;
            float v = 0.f;
            if ((unsigned)yy < 64u) v = cst[(size_t)(c0 + cc) * HW + yy * 64 + col];
            sm_c[cc][r][col + 1] = v;
        }
        {   // styles scalar
            int cc = tid >> 4, b = tid & 15;
            sm_s[cc][b] = g_s[b * CH + c0 + cc];
        }
        __syncthreads();

        #pragma unroll 4
        for (int cc = 0; cc < KC; cc++) {
            const float2* wp = &sm_w[cc][ol][0];
            float4 q0 = *(const float4*)&wp[0];   // w0,w1 dup
            float4 q1 = *(const float4*)&wp[2];   // w2,w3
            float4 q2 = *(const float4*)&wp[4];   // w4,w5
            float4 q3 = *(const float4*)&wp[6];   // w6,w7
            float2 pw8 = wp[8];

            float2 zA = make_float2(0.f, 0.f), zB = make_float2(0.f, 0.f);
            {   // row y-1: taps w0,w1,w2
                float4 a = *(const float4*)&sm_c[cc][0][x0];
                float2 e = *(const float2*)&sm_c[cc][0][x0 + 4];
                float2 pa = make_float2(q0.x, q0.y), pb = make_float2(q0.z, q0.w), pc = make_float2(q1.x, q1.y);
                float2 p0 = make_float2(a.x, a.y), p2 = make_float2(a.z, a.w), p4 = e;
                float2 m1 = make_float2(a.y, a.z), m3 = make_float2(a.w, e.x);
                fma2(zA, pa, p0, zA); fma2(zA, pb, m1, zA); fma2(zA, pc, p2, zA);
                fma2(zB, pa, p2, zB); fma2(zB, pb, m3, zB); fma2(zB, pc, p4, zB);
            }
            {   // row y: taps w3,w4,w5
                float4 a = *(const float4*)&sm_c[cc][1][x0];
                float2 e = *(const float2*)&sm_c[cc][1][x0 + 4];
                float2 pa = make_float2(q1.z, q1.w), pb = make_float2(q2.x, q2.y), pc = make_float2(q2.z, q2.w);
                float2 p0 = make_float2(a.x, a.y), p2 = make_float2(a.z, a.w), p4 = e;
                float2 m1 = make_float2(a.y, a.z), m3 = make_float2(a.w, e.x);
                fma2(zA, pa, p0, zA); fma2(zA, pb, m1, zA); fma2(zA, pc, p2, zA);
                fma2(zB, pa, p2, zB); fma2(zB, pb, m3, zB); fma2(zB, pc, p4, zB);
            }
            {   // row y+1: taps w6,w7,w8
                float4 a = *(const float4*)&sm_c[cc][2][x0];
                float2 e = *(const float2*)&sm_c[cc][2][x0 + 4];
                float2 pa = make_float2(q3.x, q3.y), pb = make_float2(q3.z, q3.w), pc = pw8;
                float2 p0 = make_float2(a.x, a.y), p2 = make_float2(a.z, a.w), p4 = e;
                float2 m1 = make_float2(a.y, a.z), m3 = make_float2(a.w, e.x);
                fma2(zA, pa, p0, zA); fma2(zA, pb, m1, zA); fma2(zA, pc, p2, zA);
                fma2(zB, pa, p2, zB); fma2(zB, pb, m3, zB); fma2(zB, pc, p4, zB);
            }
            // duplicate z per pixel (alu movs, off the fma pipe)
            float2 zd0 = make_float2(zA.x, zA.x);
            float2 zd1 = make_float2(zA.y, zA.y);
            float2 zd2 = make_float2(zB.x, zB.x);
            float2 zd3 = make_float2(zB.y, zB.y);
            // mix: batch-pair styles straight out of float4 register quads
            float4 t0 = *(const float4*)&sm_s[cc][0];
            float4 t1 = *(const float4*)&sm_s[cc][4];
            float4 t2 = *(const float4*)&sm_s[cc][8];
            float4 t3 = *(const float4*)&sm_s[cc][12];
            float2 sp[8];
            sp[0] = make_float2(t0.x, t0.y); sp[1] = make_float2(t0.z, t0.w);
            sp[2] = make_float2(t1.x, t1.y); sp[3] = make_float2(t1.z, t1.w);
            sp[4] = make_float2(t2.x, t2.y); sp[5] = make_float2(t2.z, t2.w);
            sp[6] = make_float2(t3.x, t3.y); sp[7] = make_float2(t3.z, t3.w);
            #pragma unroll
            for (int i = 0; i < 8; i++) {
                fma2(acc2[i][0], sp[i], zd0, acc2[i][0]);
                fma2(acc2[i][1], sp[i], zd1, acc2[i][1]);
                fma2(acc2[i][2], sp[i], zd2, acc2[i][2]);
                fma2(acc2[i][3], sp[i], zd3, acc2[i][3]);
            }
        }
    }

    // epilogue
    float nsv = nzs[0];
    float bo = cb[og];
    float nv[4];
    #pragma unroll
    for (int j = 0; j < 4; j++) nv[j] = fmaf(nzc[y * 64 + x0 + j], nsv, bo);
    const float gain = 1.4142135623730951f;
    size_t pxoff = (size_t)y * 64 + x0;
    #pragma unroll
    for (int i = 0; i < 8; i++) {
        int b0 = 2 * i, b1 = 2 * i + 1;
        float dc0 = g_dcoef[b0 * CH + og];
        float dc1 = g_dcoef[b1 * CH + og];
        float4 v0, v1;
        float t;
        t = fmaf(acc2[i][0].x, dc0, nv[0]); v0.x = (t > 0.f ? t : 0.2f * t) * gain;
        t = fmaf(acc2[i][1].x, dc0, nv[1]); v0.y = (t > 0.f ? t : 0.2f * t) * gain;
        t = fmaf(acc2[i][2].x, dc0, nv[2]); v0.z = (t > 0.f ? t : 0.2f * t) * gain;
        t = fmaf(acc2[i][3].x, dc0, nv[3]); v0.w = (t > 0.f ? t : 0.2f * t) * gain;
        t = fmaf(acc2[i][0].y, dc1, nv[0]); v1.x = (t > 0.f ? t : 0.2f * t) * gain;
        t = fmaf(acc2[i][1].y, dc1, nv[1]); v1.y = (t > 0.f ? t : 0.2f * t) * gain;
        t = fmaf(acc2[i][2].y, dc1, nv[2]); v1.z = (t > 0.f ? t : 0.2f * t) * gain;
        t = fmaf(acc2[i][3].y, dc1, nv[3]); v1.w = (t > 0.f ? t : 0.2f * t) * gain;
        *(float4*)(out + ((size_t)(b0 * CH + og)) * HW + pxoff) = v0;
        *(float4*)(out + ((size_t)(b1 * CH + og)) * HW + pxoff) = v1;
    }
}

// ---------------- ToRGB ----------------
__global__ void k_rgb(const float* __restrict__ x, const float* __restrict__ rgbw,
                      const float* __restrict__ rgbb, float* __restrict__ img) {
    __shared__ float rw[3][512];
    int b = blockIdx.y;
    int px = blockIdx.x * 256 + threadIdx.x;
    for (int i = threadIdx.x; i < 1536; i += 256) {
        int ch = i >> 9, o = i & 511;
        rw[ch][o] = rgbw[ch * 512 + o] * g_s2[b * 512 + o];
    }
    __syncthreads();
    const float* xp = x + (size_t)b * CH * HW + px;
    float a0 = 0.f, a1 = 0.f, a2 = 0.f;
    #pragma unroll 8
    for (int o = 0; o < 512; o++) {
        float xv = xp[(size_t)o * HW];
        a0 = fmaf(rw[0][o], xv, a0);
        a1 = fmaf(rw[1][o], xv, a1);
        a2 = fmaf(rw[2][o], xv, a2);
    }
    size_t base = (size_t)b * 3 * HW + px;
    img[base] = a0 + rgbb[0];
    img[base + HW] = a1 + rgbb[1];
    img[base + 2 * HW] = a2 + rgbb[2];
}

extern "C" void kernel_launch(void* const* d_in, const int* in_sizes, int n_in,
                              void* d_out, int out_size) {
    const float* ws   = (const float*)d_in[0];
    const float* cst  = (const float*)d_in[1];
    const float* cw   = (const float*)d_in[2];
    const float* cb   = (const float*)d_in[3];
    const float* caw  = (const float*)d_in[4];
    const float* cab  = (const float*)d_in[5];
    const float* nzc  = (const float*)d_in[6];
    const float* nzs  = (const float*)d_in[7];
    const float* rgbw = (const float*)d_in[8];
    const float* rgbb = (const float*)d_in[9];
    const float* raw  = (const float*)d_in[10];
    const float* rab  = (const float*)d_in[11];
    float* out = (float*)d_out;

    k_style<<<1024, 256>>>(ws, caw, cab, raw, rab);
    k_wsq<<<1024, 256>>>(cw);
    k_dcoef<<<1024, 256>>>();
    dim3 g(64, 32);
    k_main<<<g, NTHR>>>(cst, cw, cb, nzc, nzs, out);
    k_rgb<<<dim3(16, 16), 256>>>(out, rgbw, rgbb, out + (size_t)BATCH * CH * HW);
}

// round 4
// speedup vs baseline: 1.4851x; 1.3272x over previous
#include <cuda_runtime.h>
#include <math.h>

#define BATCH 16
#define CH 512
#define RES 64
#define HW 4096
#define OT 16     // output channels per CTA
#define KC 32     // c-chunk
#define NTHR 256

__device__ float g_s[BATCH * CH];      // conv styles [b][c] (for dcoef)
__device__ float g_st[CH * BATCH];     // conv styles transposed [c][b] (copied to cbank)
__device__ float g_s2[BATCH * CH];     // rgb styles
__device__ float g_dcoef[BATCH * CH];  // demod coefficients
__device__ float g_wsq[CH * CH];

__constant__ float4 c_s4[CH * 4];      // styles cc-major: c_s4[c*4+q] = s[b=4q..4q+3][c]

// packed fp32x2 FMA
__device__ __forceinline__ void fma2(float2& d, float2 a, float2 b, float2 c) {
    asm("fma.rn.f32x2 %0, %1, %2, %3;"
        : "=l"(reinterpret_cast<unsigned long long&>(d))
        : "l"(reinterpret_cast<unsigned long long&>(a)),
          "l"(reinterpret_cast<unsigned long long&>(b)),
          "l"(reinterpret_cast<unsigned long long&>(c)));
}

// ---------------- styles ----------------
__global__ void k_style(const float* __restrict__ ws, const float* __restrict__ caw,
                        const float* __restrict__ cab, const float* __restrict__ raw,
                        const float* __restrict__ rab) {
    int widx = blockIdx.x * 8 + (threadIdx.x >> 5);
    int lane = threadIdx.x & 31;
    int b = widx >> 9, c = widx & 511;
    const float* w0 = ws + b * 1024;
    const float* w1 = w0 + 512;
    const float* ca = caw + c * 512;
    const float* ra = raw + c * 512;
    float a1 = 0.f, a2 = 0.f;
    for (int d = lane; d < 512; d += 32) {
        a1 = fmaf(w0[d], ca[d], a1);
        a2 = fmaf(w1[d], ra[d], a2);
    }
    #pragma unroll
    for (int o = 16; o; o >>= 1) {
        a1 += __shfl_xor_sync(0xffffffffu, a1, o);
        a2 += __shfl_xor_sync(0xffffffffu, a2, o);
    }
    if (lane == 0) {
        g_s[b * 512 + c] = a1 + cab[c];
        g_st[c * 16 + b] = a1 + cab[c];
        g_s2[b * 512 + c] = (a2 + rab[c]) * 0.04419417382415922f;
    }
}

// ---------------- wsq ----------------
__global__ void k_wsq(const float* __restrict__ cw) {
    int idx = blockIdx.x * 256 + threadIdx.x;
    const float* p = cw + (size_t)idx * 9;
    float s = 0.f;
    #pragma unroll
    for (int k = 0; k < 9; k++) s = fmaf(p[k], p[k], s);
    g_wsq[idx] = s;
}

// ---------------- dcoef ----------------
__global__ void k_dcoef() {
    int widx = blockIdx.x * 8 + (threadIdx.x >> 5);
    int lane = threadIdx.x & 31;
    int b = widx >> 9, o = widx & 511;
    const float* wq = g_wsq + o * 512;
    const float* sp = g_s + b * 512;
    float a = 0.f;
    for (int c = lane; c < 512; c += 32) {
        float sv = sp[c];
        a = fmaf(wq[c] * sv, sv, a);
    }
    #pragma unroll
    for (int off = 16; off; off >>= 1) a += __shfl_xor_sync(0xffffffffu, a, off);
    if (!lane) g_dcoef[b * 512 + o] = rsqrtf(a + 1e-8f);
}

// ---------------- main fused kernel ----------------
// CTA: one row y, 16 output channels, all 16 batches. 256 threads, 2 CTAs/SM.
// Styles come from the CONSTANT bank (separate port) — zero LDS crossbar cost.
__global__ __launch_bounds__(NTHR, 2)
void k_main(const float* __restrict__ cst, const float* __restrict__ cw,
            const float* __restrict__ cb, const float* __restrict__ nzc,
            const float* __restrict__ nzs, float* __restrict__ out) {
    __shared__ float sm_w[KC][OT][12];   // scalar taps, pad 9->12 for f4 alignment
    __shared__ float sm_c[KC][3][72];    // halo-padded const rows

    const int y = blockIdx.x;
    const int obase = blockIdx.y * OT;
    const int tid = threadIdx.x;
    const int ol = tid >> 4;       // 0..15 output channel within tile
    const int pg = tid & 15;
    const int x0 = pg << 2;        // 4 contiguous pixels
    const int og = obase + ol;

    if (tid < KC * 3) {
        sm_c[tid / 3][tid % 3][0] = 0.f;
        sm_c[tid / 3][tid % 3][65] = 0.f;
    }

    float2 acc2[8][4];             // [batch-pair][pixel]
    #pragma unroll
    for (int i = 0; i < 8; i++)
        #pragma unroll
        for (int j = 0; j < 4; j++) acc2[i][j] = make_float2(0.f, 0.f);

    for (int c0 = 0; c0 < CH; c0 += KC) {
        __syncthreads();
        {   // weights scalar: 512 (oo,cc) slots over 256 threads, 2 each
            #pragma unroll
            for (int sl = 0; sl < 2; sl++) {
                int slot = tid + sl * NTHR;
                int oo = slot >> 5;
                int cc = slot & 31;
                const float* gp = cw + ((size_t)(obase + oo) * CH + (c0 + cc)) * 9;
                #pragma unroll
                for (int k = 0; k < 9; k++) sm_w[cc][oo][k] = gp[k];
            }
        }
        // const rows y-1..y+1 for KC channels: 6144 elems over 256 threads
        #pragma unroll
        for (int it = 0; it < 24; it++) {
            int i = tid + it * NTHR;
            int cc = i / 192;
            int rem = i - cc * 192;
            int r = rem >> 6;
            int col = rem & 63;
            int yy = y + r - 1;
            float v = 0.f;
            if ((unsigned)yy < 64u) v = cst[(size_t)(c0 + cc) * HW + yy * 64 + col];
            sm_c[cc][r][col + 1] = v;
        }
        __syncthreads();

        #pragma unroll 4
        for (int cc = 0; cc < KC; cc++) {
            const float* wp = &sm_w[cc][ol][0];
            float4 wa = *(const float4*)&wp[0];   // w0..w3
            float4 wb = *(const float4*)&wp[4];   // w4..w7
            float  w8 = wp[8];

            float2 zA = make_float2(0.f, 0.f), zB = make_float2(0.f, 0.f);
            {   // row y-1: taps w0,w1,w2
                float4 a = *(const float4*)&sm_c[cc][0][x0];
                float2 e = *(const float2*)&sm_c[cc][0][x0 + 4];
                float2 pa = make_float2(wa.x, wa.x), pb = make_float2(wa.y, wa.y), pc = make_float2(wa.z, wa.z);
                float2 p0 = make_float2(a.x, a.y), p2 = make_float2(a.z, a.w), p4 = e;
                float2 m1 = make_float2(a.y, a.z), m3 = make_float2(a.w, e.x);
                fma2(zA, pa, p0, zA); fma2(zA, pb, m1, zA); fma2(zA, pc, p2, zA);
                fma2(zB, pa, p2, zB); fma2(zB, pb, m3, zB); fma2(zB, pc, p4, zB);
            }
            {   // row y: taps w3,w4,w5
                float4 a = *(const float4*)&sm_c[cc][1][x0];
                float2 e = *(const float2*)&sm_c[cc][1][x0 + 4];
                float2 pa = make_float2(wa.w, wa.w), pb = make_float2(wb.x, wb.x), pc = make_float2(wb.y, wb.y);
                float2 p0 = make_float2(a.x, a.y), p2 = make_float2(a.z, a.w), p4 = e;
                float2 m1 = make_float2(a.y, a.z), m3 = make_float2(a.w, e.x);
                fma2(zA, pa, p0, zA); fma2(zA, pb, m1, zA); fma2(zA, pc, p2, zA);
                fma2(zB, pa, p2, zB); fma2(zB, pb, m3, zB); fma2(zB, pc, p4, zB);
            }
            {   // row y+1: taps w6,w7,w8
                float4 a = *(const float4*)&sm_c[cc][2][x0];
                float2 e = *(const float2*)&sm_c[cc][2][x0 + 4];
                float2 pa = make_float2(wb.z, wb.z), pb = make_float2(wb.w, wb.w), pc = make_float2(w8, w8);
                float2 p0 = make_float2(a.x, a.y), p2 = make_float2(a.z, a.w), p4 = e;
                float2 m1 = make_float2(a.y, a.z), m3 = make_float2(a.w, e.x);
                fma2(zA, pa, p0, zA); fma2(zA, pb, m1, zA); fma2(zA, pc, p2, zA);
                fma2(zB, pa, p2, zB); fma2(zB, pb, m3, zB); fma2(zB, pc, p4, zB);
            }
            // duplicate z per pixel (alu movs)
            float2 zd0 = make_float2(zA.x, zA.x);
            float2 zd1 = make_float2(zA.y, zA.y);
            float2 zd2 = make_float2(zB.x, zB.x);
            float2 zd3 = make_float2(zB.y, zB.y);
            // styles from CONSTANT bank (separate port, no crossbar traffic)
            int cb4 = (c0 + cc) * 4;
            float4 t0 = c_s4[cb4 + 0];
            float4 t1 = c_s4[cb4 + 1];
            float4 t2 = c_s4[cb4 + 2];
            float4 t3 = c_s4[cb4 + 3];
            float2 sp[8];
            sp[0] = make_float2(t0.x, t0.y); sp[1] = make_float2(t0.z, t0.w);
            sp[2] = make_float2(t1.x, t1.y); sp[3] = make_float2(t1.z, t1.w);
            sp[4] = make_float2(t2.x, t2.y); sp[5] = make_float2(t2.z, t2.w);
            sp[6] = make_float2(t3.x, t3.y); sp[7] = make_float2(t3.z, t3.w);
            #pragma unroll
            for (int i = 0; i < 8; i++) {
                fma2(acc2[i][0], sp[i], zd0, acc2[i][0]);
                fma2(acc2[i][1], sp[i], zd1, acc2[i][1]);
                fma2(acc2[i][2], sp[i], zd2, acc2[i][2]);
                fma2(acc2[i][3], sp[i], zd3, acc2[i][3]);
            }
        }
    }

    // epilogue
    float nsv = nzs[0];
    float bo = cb[og];
    float nv[4];
    #pragma unroll
    for (int j = 0; j < 4; j++) nv[j] = fmaf(nzc[y * 64 + x0 + j], nsv, bo);
    const float gain = 1.4142135623730951f;
    size_t pxoff = (size_t)y * 64 + x0;
    #pragma unroll
    for (int i = 0; i < 8; i++) {
        int b0 = 2 * i, b1 = 2 * i + 1;
        float dc0 = g_dcoef[b0 * CH + og];
        float dc1 = g_dcoef[b1 * CH + og];
        float4 v0, v1;
        float t;
        t = fmaf(acc2[i][0].x, dc0, nv[0]); v0.x = (t > 0.f ? t : 0.2f * t) * gain;
        t = fmaf(acc2[i][1].x, dc0, nv[1]); v0.y = (t > 0.f ? t : 0.2f * t) * gain;
        t = fmaf(acc2[i][2].x, dc0, nv[2]); v0.z = (t > 0.f ? t : 0.2f * t) * gain;
        t = fmaf(acc2[i][3].x, dc0, nv[3]); v0.w = (t > 0.f ? t : 0.2f * t) * gain;
        t = fmaf(acc2[i][0].y, dc1, nv[0]); v1.x = (t > 0.f ? t : 0.2f * t) * gain;
        t = fmaf(acc2[i][1].y, dc1, nv[1]); v1.y = (t > 0.f ? t : 0.2f * t) * gain;
        t = fmaf(acc2[i][2].y, dc1, nv[2]); v1.z = (t > 0.f ? t : 0.2f * t) * gain;
        t = fmaf(acc2[i][3].y, dc1, nv[3]); v1.w = (t > 0.f ? t : 0.2f * t) * gain;
        *(float4*)(out + ((size_t)(b0 * CH + og)) * HW + pxoff) = v0;
        *(float4*)(out + ((size_t)(b1 * CH + og)) * HW + pxoff) = v1;
    }
}

// ---------------- ToRGB ----------------
__global__ void k_rgb(const float* __restrict__ x, const float* __restrict__ rgbw,
                      const float* __restrict__ rgbb, float* __restrict__ img) {
    __shared__ float rw[3][512];
    int b = blockIdx.y;
    int px = blockIdx.x * 256 + threadIdx.x;
    for (int i = threadIdx.x; i < 1536; i += 256) {
        int ch = i >> 9, o = i & 511;
        rw[ch][o] = rgbw[ch * 512 + o] * g_s2[b * 512 + o];
    }
    __syncthreads();
    const float* xp = x + (size_t)b * CH * HW + px;
    float a0 = 0.f, a1 = 0.f, a2 = 0.f;
    #pragma unroll 8
    for (int o = 0; o < 512; o++) {
        float xv = xp[(size_t)o * HW];
        a0 = fmaf(rw[0][o], xv, a0);
        a1 = fmaf(rw[1][o], xv, a1);
        a2 = fmaf(rw[2][o], xv, a2);
    }
    size_t base = (size_t)b * 3 * HW + px;
    img[base] = a0 + rgbb[0];
    img[base + HW] = a1 + rgbb[1];
    img[base + 2 * HW] = a2 + rgbb[2];
}

extern "C" void kernel_launch(void* const* d_in, const int* in_sizes, int n_in,
                              void* d_out, int out_size) {
    const float* ws   = (const float*)d_in[0];
    const float* cst  = (const float*)d_in[1];
    const float* cw   = (const float*)d_in[2];
    const float* cb   = (const float*)d_in[3];
    const float* caw  = (const float*)d_in[4];
    const float* cab  = (const float*)d_in[5];
    const float* nzc  = (const float*)d_in[6];
    const float* nzs  = (const float*)d_in[7];
    const float* rgbw = (const float*)d_in[8];
    const float* rgbb = (const float*)d_in[9];
    const float* raw  = (const float*)d_in[10];
    const float* rab  = (const float*)d_in[11];
    float* out = (float*)d_out;

    k_style<<<1024, 256>>>(ws, caw, cab, raw, rab);
    k_wsq<<<1024, 256>>>(cw);
    k_dcoef<<<1024, 256>>>();

    // copy computed styles (device global) into the constant bank — D2D async,
    // graph-capturable memcpy node, stream-ordered after k_style.
    void* src = nullptr;
    cudaGetSymbolAddress(&src, g_st);
    cudaMemcpyToSymbolAsync(c_s4, src, CH * BATCH * sizeof(float), 0,
                            cudaMemcpyDeviceToDevice, 0);

    dim3 g(64, 32);
    k_main<<<g, NTHR>>>(cst, cw, cb, nzc, nzs, out);
    k_rgb<<<dim3(16, 16), 256>>>(out, rgbw, rgbb, out + (size_t)BATCH * CH * HW);
}

// round 6
// speedup vs baseline: 1.6611x; 1.1185x over previous
#include <cuda_runtime.h>
#include <cuda_fp16.h>
#include <math.h>
#include <stdint.h>

#define BATCH 16
#define CH 512
#define HW 4096
#define KTOT 4608           // 512 c * 9 taps
#define KITERS 144          // 4608 / 32
#define GTHR 256

// ---------------- scratch ----------------
__device__ float g_s[BATCH * CH];
__device__ float g_s2[BATCH * CH];
__device__ float g_dcoef[BATCH * CH];
__device__ float g_wsq[CH * CH];
__device__ __half g_A[BATCH * CH * KTOT];   // modulated weights [b][o][ck] (75MB)
__device__ __half g_B[HW * KTOT];           // im2col patches  [p][ck]    (37.7MB)

__device__ __forceinline__ uint32_t s2u(const void* p) {
    return (uint32_t)__cvta_generic_to_shared(p);
}
// swizzled 16B-chunk offset within a 64B row
__device__ __forceinline__ uint32_t swzoff(uint32_t row, uint32_t chunk) {
    return row * 64u + ((chunk ^ ((row >> 1) & 3u)) << 4);
}
__device__ __forceinline__ void cpa16(uint32_t s, const void* g) {
    asm volatile("cp.async.cg.shared.global [%0], [%1], 16;" :: "r"(s), "l"(g));
}
__device__ __forceinline__ void ldm4(uint32_t addr, uint32_t& r0, uint32_t& r1,
                                     uint32_t& r2, uint32_t& r3) {
    asm volatile("ldmatrix.sync.aligned.m8n8.x4.shared.b16 {%0,%1,%2,%3}, [%4];"
                 : "=r"(r0), "=r"(r1), "=r"(r2), "=r"(r3) : "r"(addr));
}
__device__ __forceinline__ void hmma(float* d, const uint32_t* a, const uint32_t* bf) {
    asm volatile(
        "mma.sync.aligned.m16n8k16.row.col.f32.f16.f16.f32 "
        "{%0,%1,%2,%3}, {%4,%5,%6,%7}, {%8,%9}, {%0,%1,%2,%3};"
        : "+f"(d[0]), "+f"(d[1]), "+f"(d[2]), "+f"(d[3])
        : "r"(a[0]), "r"(a[1]), "r"(a[2]), "r"(a[3]), "r"(bf[0]), "r"(bf[1]));
}

// ---------------- styles ----------------
__global__ void k_style(const float* __restrict__ ws, const float* __restrict__ caw,
                        const float* __restrict__ cab, const float* __restrict__ raw,
                        const float* __restrict__ rab) {
    int widx = blockIdx.x * 8 + (threadIdx.x >> 5);
    int lane = threadIdx.x & 31;
    int b = widx >> 9, c = widx & 511;
    const float* w0 = ws + b * 1024;
    const float* w1 = w0 + 512;
    const float* ca = caw + c * 512;
    const float* ra = raw + c * 512;
    float a1 = 0.f, a2 = 0.f;
    for (int d = lane; d < 512; d += 32) {
        a1 = fmaf(w0[d], ca[d], a1);
        a2 = fmaf(w1[d], ra[d], a2);
    }
    #pragma unroll
    for (int o = 16; o; o >>= 1) {
        a1 += __shfl_xor_sync(0xffffffffu, a1, o);
        a2 += __shfl_xor_sync(0xffffffffu, a2, o);
    }
    if (lane == 0) {
        g_s[b * 512 + c] = a1 + cab[c];
        g_s2[b * 512 + c] = (a2 + rab[c]) * 0.04419417382415922f;
    }
}

// ---------------- wsq ----------------
__global__ void k_wsq(const float* __restrict__ cw) {
    int idx = blockIdx.x * 256 + threadIdx.x;
    const float* p = cw + (size_t)idx * 9;
    float s = 0.f;
    #pragma unroll
    for (int k = 0; k < 9; k++) s = fmaf(p[k], p[k], s);
    g_wsq[idx] = s;
}

// ---------------- dcoef ----------------
__global__ void k_dcoef() {
    int widx = blockIdx.x * 8 + (threadIdx.x >> 5);
    int lane = threadIdx.x & 31;
    int b = widx >> 9, o = widx & 511;
    const float* wq = g_wsq + o * 512;
    const float* sp = g_s + b * 512;
    float a = 0.f;
    for (int c = lane; c < 512; c += 32) {
        float sv = sp[c];
        a = fmaf(wq[c] * sv, sv, a);
    }
    #pragma unroll
    for (int off = 16; off; off >>= 1) a += __shfl_xor_sync(0xffffffffu, a, off);
    if (!lane) g_dcoef[b * 512 + o] = rsqrtf(a + 1e-8f);
}

// ---------------- A prep ----------------
__global__ void k_aprep(const float* __restrict__ cw) {
    int idx = blockIdx.x * 256 + threadIdx.x;
    int ck = idx % KTOT;
    int rem = idx / KTOT;
    int o = rem & 511;
    int b = rem >> 9;
    int c = ck / 9;
    float v = cw[(size_t)o * KTOT + ck] * g_s[b * 512 + c];
    g_A[idx] = __float2half_rn(v);
}

// ---------------- B prep: im2col ----------------
__global__ void k_bprep(const float* __restrict__ cst) {
    int idx = blockIdx.x * 256 + threadIdx.x;
    int ck = idx % KTOT;
    int p = idx / KTOT;
    int c = ck / 9;
    int k = ck - c * 9;
    int ky = k / 3, kx = k - ky * 3;
    int yy = (p >> 6) + ky - 1;
    int xx = (p & 63) + kx - 1;
    float v = 0.f;
    if ((unsigned)yy < 64u && (unsigned)xx < 64u)
        v = cst[c * 4096 + yy * 64 + xx];
    g_B[idx] = __float2half_rn(v);
}

// ---------------- main GEMM: mma.sync m16n8k16, CTA 128x256, warp 64x64 ----------------
#define SA_BYTES 8192      // 128 x 32 fp16
#define SB_BYTES 16384     // 256 x 32 fp16

__global__ __launch_bounds__(GTHR, 1)
void k_gemm(const float* __restrict__ nzc, const float* __restrict__ nzs,
            const float* __restrict__ cb, float* __restrict__ out) {
    __shared__ char smem[2 * (SA_BYTES + SB_BYTES)];   // A0 A1 B0 B1
    const uint32_t sb = s2u(smem);
    const uint32_t sA[2] = {sb, sb + SA_BYTES};
    const uint32_t sB[2] = {sb + 2 * SA_BYTES, sb + 2 * SA_BYTES + SB_BYTES};

    const int tid = threadIdx.x;
    const int wid = tid >> 5;
    const int lane = tid & 31;
    const int wm = wid & 1;        // 2 m-bands of 64
    const int wn = wid >> 1;       // 4 n-bands of 64

    const int b = blockIdx.z;
    const int obase = blockIdx.y * 128;
    const int pbase = blockIdx.x * 256;

    const char* Ag = (const char*)(g_A + (size_t)(b * 512 + obase) * KTOT);
    const char* Bg = (const char*)(g_B + (size_t)pbase * KTOT);

    float acc[4][8][4];
    #pragma unroll
    for (int mi = 0; mi < 4; mi++)
        #pragma unroll
        for (int nj = 0; nj < 8; nj++)
            #pragma unroll
            for (int q = 0; q < 4; q++) acc[mi][nj][q] = 0.f;

    // fill helper (macro to keep addresses in regs)
    #define FILL(KI, BUF) do {                                                    \
        size_t kb = (size_t)(KI) * 64;  /* bytes into each K row (32 fp16) */     \
        _Pragma("unroll")                                                         \
        for (int j = 0; j < 2; j++) {                                             \
            int idx = tid + j * GTHR;                                             \
            uint32_t row = idx >> 2, cv = idx & 3;                                \
            cpa16(sA[BUF] + swzoff(row, cv),                                      \
                  Ag + (size_t)row * (KTOT * 2) + kb + cv * 16);                  \
        }                                                                         \
        _Pragma("unroll")                                                         \
        for (int j = 0; j < 4; j++) {                                             \
            int idx = tid + j * GTHR;                                             \
            uint32_t row = idx >> 2, cv = idx & 3;                                \
            cpa16(sB[BUF] + swzoff(row, cv),                                      \
                  Bg + (size_t)row * (KTOT * 2) + kb + cv * 16);                  \
        }                                                                         \
        asm volatile("cp.async.commit_group;" ::: "memory");                      \
    } while (0)

    FILL(0, 0);

    for (int i = 0; i < KITERS; i++) {
        const int buf = i & 1;
        if (i + 1 < KITERS) {
            FILL(i + 1, buf ^ 1);
            asm volatile("cp.async.wait_group 1;" ::: "memory");
        } else {
            asm volatile("cp.async.wait_group 0;" ::: "memory");
        }
        __syncthreads();

        #pragma unroll
        for (int k16 = 0; k16 < 2; k16++) {
            const uint32_t kc = k16 * 2;
            uint32_t a[4][4], br[4][4];
            #pragma unroll
            for (int mi = 0; mi < 4; mi++) {
                uint32_t row = wm * 64 + mi * 16 + (lane & 15);
                uint32_t chunk = kc + (lane >> 4);
                ldm4(sA[buf] + swzoff(row, chunk), a[mi][0], a[mi][1], a[mi][2], a[mi][3]);
            }
            #pragma unroll
            for (int njp = 0; njp < 4; njp++) {
                uint32_t row = wn * 64 + njp * 16 + ((lane >> 4) << 3) + (lane & 7);
                uint32_t chunk = kc + ((lane >> 3) & 1);
                ldm4(sB[buf] + swzoff(row, chunk), br[njp][0], br[njp][1], br[njp][2], br[njp][3]);
            }
            #pragma unroll
            for (int mi = 0; mi < 4; mi++)
                #pragma unroll
                for (int nj = 0; nj < 8; nj++)
                    hmma(acc[mi][nj], a[mi], &br[nj >> 1][(nj & 1) * 2]);
        }
        __syncthreads();
    }

    // ---------------- fused epilogue ----------------
    const float nst = nzs[0];
    const float gain = 1.4142135623730951f;
    const int r0 = lane >> 2;
    const int cpair = (lane & 3) * 2;

    float nzv[8][2];
    #pragma unroll
    for (int nj = 0; nj < 8; nj++) {
        int p = pbase + wn * 64 + nj * 8 + cpair;
        nzv[nj][0] = nzc[p] * nst;
        nzv[nj][1] = nzc[p + 1] * nst;
    }

    #pragma unroll
    for (int mi = 0; mi < 4; mi++) {
        #pragma unroll
        for (int h = 0; h < 2; h++) {
            int o = obase + wm * 64 + mi * 16 + h * 8 + r0;
            float dc = g_dcoef[b * 512 + o];
            float bias = cb[o];
            float* orow = out + (size_t)(b * 512 + o) * HW;
            #pragma unroll
            for (int nj = 0; nj < 8; nj++) {
                int p = pbase + wn * 64 + nj * 8 + cpair;
                float z0 = fmaf(acc[mi][nj][2 * h],     dc, nzv[nj][0] + bias);
                float z1 = fmaf(acc[mi][nj][2 * h + 1], dc, nzv[nj][1] + bias);
                float2 v;
                v.x = (z0 > 0.f ? z0 : 0.2f * z0) * gain;
                v.y = (z1 > 0.f ? z1 : 0.2f * z1) * gain;
                *(float2*)(orow + p) = v;
            }
        }
    }
}

// ---------------- ToRGB ----------------
__global__ void k_rgb(const float* __restrict__ x, const float* __restrict__ rgbw,
                      const float* __restrict__ rgbb, float* __restrict__ img) {
    __shared__ float rw[3][512];
    int b = blockIdx.y;
    int px = blockIdx.x * 256 + threadIdx.x;
    for (int i = threadIdx.x; i < 1536; i += 256) {
        int ch = i >> 9, o = i & 511;
        rw[ch][o] = rgbw[ch * 512 + o] * g_s2[b * 512 + o];
    }
    __syncthreads();
    const float* xp = x + (size_t)b * CH * HW + px;
    float a0 = 0.f, a1 = 0.f, a2 = 0.f;
    #pragma unroll 8
    for (int o = 0; o < 512; o++) {
        float xv = xp[(size_t)o * HW];
        a0 = fmaf(rw[0][o], xv, a0);
        a1 = fmaf(rw[1][o], xv, a1);
        a2 = fmaf(rw[2][o], xv, a2);
    }
    size_t base = (size_t)b * 3 * HW + px;
    img[base] = a0 + rgbb[0];
    img[base + HW] = a1 + rgbb[1];
    img[base + 2 * HW] = a2 + rgbb[2];
}

extern "C" void kernel_launch(void* const* d_in, const int* in_sizes, int n_in,
                              void* d_out, int out_size) {
    const float* ws   = (const float*)d_in[0];
    const float* cst  = (const float*)d_in[1];
    const float* cw   = (const float*)d_in[2];
    const float* cb   = (const float*)d_in[3];
    const float* caw  = (const float*)d_in[4];
    const float* cab  = (const float*)d_in[5];
    const float* nzc  = (const float*)d_in[6];
    const float* nzs  = (const float*)d_in[7];
    const float* rgbw = (const float*)d_in[8];
    const float* rgbb = (const float*)d_in[9];
    const float* raw  = (const float*)d_in[10];
    const float* rab  = (const float*)d_in[11];
    float* out = (float*)d_out;

    k_style<<<1024, 256>>>(ws, caw, cab, raw, rab);
    k_wsq<<<1024, 256>>>(cw);
    k_dcoef<<<1024, 256>>>();
    k_aprep<<<BATCH * CH * KTOT / 256, 256>>>(cw);
    k_bprep<<<HW * KTOT / 256, 256>>>(cst);

    dim3 g(HW / 256, CH / 128, BATCH);   // (16, 4, 16) = 1024 CTAs
    k_gemm<<<g, GTHR>>>(nzc, nzs, cb, out);

    k_rgb<<<dim3(16, 16), 256>>>(out, rgbw, rgbb, out + (size_t)BATCH * CH * HW);
}

// round 7
// speedup vs baseline: 2.2892x; 1.3781x over previous
#include <cuda_runtime.h>
#include <cuda_fp16.h>
#include <math.h>
#include <stdint.h>

#define BATCH 16
#define CH 512
#define HW 4096
#define KTOT 4608           // 512 c * 9 taps
#define KC64 64             // K per stage (fp16) = 128B row
#define KITERS 72           // 4608 / 64
#define GTHR 256
#define STAGES 3
#define A_BYTES 16384       // 128 x 64 fp16
#define B_BYTES 32768       // 256 x 64 fp16
#define STAGE_BYTES (A_BYTES + B_BYTES)
#define SMEM_GEMM (STAGES * STAGE_BYTES)

// ---------------- scratch ----------------
__device__ float g_s[BATCH * CH];
__device__ float g_s2[BATCH * CH];
__device__ float g_dcoef[BATCH * CH];
__device__ float g_wsq[CH * CH];
__device__ __half g_A[BATCH * CH * KTOT];   // modulated weights [b][o][ck]
__device__ __half g_B[HW * KTOT];           // im2col patches  [p][ck]

__device__ __forceinline__ uint32_t s2u(const void* p) {
    return (uint32_t)__cvta_generic_to_shared(p);
}
// 128B rows, XOR-8 swizzle on 16B chunks
__device__ __forceinline__ uint32_t swzoff(uint32_t row, uint32_t chunk) {
    return row * 128u + ((chunk ^ (row & 7u)) << 4);
}
__device__ __forceinline__ void cpa16(uint32_t s, const void* g) {
    asm volatile("cp.async.cg.shared.global [%0], [%1], 16;" :: "r"(s), "l"(g));
}
__device__ __forceinline__ void ldm4(uint32_t addr, uint32_t& r0, uint32_t& r1,
                                     uint32_t& r2, uint32_t& r3) {
    asm volatile("ldmatrix.sync.aligned.m8n8.x4.shared.b16 {%0,%1,%2,%3}, [%4];"
                 : "=r"(r0), "=r"(r1), "=r"(r2), "=r"(r3) : "r"(addr));
}
__device__ __forceinline__ void hmma(float* d, const uint32_t* a, const uint32_t* bf) {
    asm volatile(
        "mma.sync.aligned.m16n8k16.row.col.f32.f16.f16.f32 "
        "{%0,%1,%2,%3}, {%4,%5,%6,%7}, {%8,%9}, {%0,%1,%2,%3};"
        : "+f"(d[0]), "+f"(d[1]), "+f"(d[2]), "+f"(d[3])
        : "r"(a[0]), "r"(a[1]), "r"(a[2]), "r"(a[3]), "r"(bf[0]), "r"(bf[1]));
}

// ---------------- styles ----------------
__global__ void k_style(const float* __restrict__ ws, const float* __restrict__ caw,
                        const float* __restrict__ cab, const float* __restrict__ raw,
                        const float* __restrict__ rab) {
    int widx = blockIdx.x * 8 + (threadIdx.x >> 5);
    int lane = threadIdx.x & 31;
    int b = widx >> 9, c = widx & 511;
    const float* w0 = ws + b * 1024;
    const float* w1 = w0 + 512;
    const float* ca = caw + c * 512;
    const float* ra = raw + c * 512;
    float a1 = 0.f, a2 = 0.f;
    for (int d = lane; d < 512; d += 32) {
        a1 = fmaf(w0[d], ca[d], a1);
        a2 = fmaf(w1[d], ra[d], a2);
    }
    #pragma unroll
    for (int o = 16; o; o >>= 1) {
        a1 += __shfl_xor_sync(0xffffffffu, a1, o);
        a2 += __shfl_xor_sync(0xffffffffu, a2, o);
    }
    if (lane == 0) {
        g_s[b * 512 + c] = a1 + cab[c];
        g_s2[b * 512 + c] = (a2 + rab[c]) * 0.04419417382415922f;
    }
}

// ---------------- wsq ----------------
__global__ void k_wsq(const float* __restrict__ cw) {
    int idx = blockIdx.x * 256 + threadIdx.x;
    const float* p = cw + (size_t)idx * 9;
    float s = 0.f;
    #pragma unroll
    for (int k = 0; k < 9; k++) s = fmaf(p[k], p[k], s);
    g_wsq[idx] = s;
}

// ---------------- dcoef ----------------
__global__ void k_dcoef() {
    int widx = blockIdx.x * 8 + (threadIdx.x >> 5);
    int lane = threadIdx.x & 31;
    int b = widx >> 9, o = widx & 511;
    const float* wq = g_wsq + o * 512;
    const float* sp = g_s + b * 512;
    float a = 0.f;
    for (int c = lane; c < 512; c += 32) {
        float sv = sp[c];
        a = fmaf(wq[c] * sv, sv, a);
    }
    #pragma unroll
    for (int off = 16; off; off >>= 1) a += __shfl_xor_sync(0xffffffffu, a, off);
    if (!lane) g_dcoef[b * 512 + o] = rsqrtf(a + 1e-8f);
}

// ---------------- A prep: vectorized x8 ----------------
__global__ void k_aprep(const float* __restrict__ cw) {
    int idx = blockIdx.x * 256 + threadIdx.x;        // over 16*512*4608/8
    int ck8 = (idx % (KTOT / 8)) * 8;
    int rem = idx / (KTOT / 8);
    int o = rem & 511;
    int b = rem >> 9;
    const float* sp = g_s + b * 512;
    const float* wp = cw + (size_t)o * KTOT + ck8;
    float4 f0 = *(const float4*)(wp);
    float4 f1 = *(const float4*)(wp + 4);
    __half h[8];
    #pragma unroll
    for (int j = 0; j < 8; j++) {
        int c = (unsigned)(ck8 + j) / 9u;
        float wv = (j < 4) ? ((const float*)&f0)[j] : ((const float*)&f1)[j - 4];
        h[j] = __float2half_rn(wv * sp[c]);
    }
    *(uint4*)(g_A + (size_t)idx * 8) = *(const uint4*)h;
}

// ---------------- B prep: im2col, vectorized x4 ----------------
__global__ void k_bprep(const float* __restrict__ cst) {
    int idx = blockIdx.x * 256 + threadIdx.x;        // over 4096*4608/4
    int ck4 = (idx % (KTOT / 4)) * 4;
    int p = idx / (KTOT / 4);
    int py = p >> 6, px = p & 63;
    __half h[4];
    #pragma unroll
    for (int j = 0; j < 4; j++) {
        int ck = ck4 + j;
        int c = (unsigned)ck / 9u;
        int k = ck - c * 9;
        int ky = (unsigned)k / 3u;
        int kx = k - ky * 3;
        int yy = py + ky - 1;
        int xx = px + kx - 1;
        float v = 0.f;
        if ((unsigned)yy < 64u && (unsigned)xx < 64u)
            v = cst[c * 4096 + yy * 64 + xx];
        h[j] = __float2half_rn(v);
    }
    *(uint2*)(g_B + (size_t)idx * 4) = *(const uint2*)h;
}

// ---------------- main GEMM: 3-stage pipeline, K-chunk 64 ----------------
__global__ __launch_bounds__(GTHR, 1)
void k_gemm(const float* __restrict__ nzc, const float* __restrict__ nzs,
            const float* __restrict__ cb, float* __restrict__ out) {
    extern __shared__ char smem[];
    const uint32_t sb = s2u(smem);

    const int tid = threadIdx.x;
    const int wid = tid >> 5;
    const int lane = tid & 31;
    const int wm = wid & 1;        // 2 m-bands of 64
    const int wn = wid >> 1;       // 4 n-bands of 64

    const int b = blockIdx.z;
    const int obase = blockIdx.y * 128;
    const int pbase = blockIdx.x * 256;

    const char* Ag = (const char*)(g_A + (size_t)(b * 512 + obase) * KTOT);
    const char* Bg = (const char*)(g_B + (size_t)pbase * KTOT);

    float acc[4][8][4];
    #pragma unroll
    for (int mi = 0; mi < 4; mi++)
        #pragma unroll
        for (int nj = 0; nj < 8; nj++)
            #pragma unroll
            for (int q = 0; q < 4; q++) acc[mi][nj][q] = 0.f;

    // fill one stage: A 1024 chunk-loads, B 2048 chunk-loads over 256 threads
    #define FILL(KI, STG) do {                                                    \
        size_t kb = (size_t)(KI) * 128;                                           \
        uint32_t sA = sb + (STG) * STAGE_BYTES;                                   \
        uint32_t sBs = sA + A_BYTES;                                              \
        _Pragma("unroll")                                                         \
        for (int j = 0; j < 4; j++) {                                             \
            int idx = tid + j * GTHR;                                             \
            uint32_t row = idx >> 3, cv = idx & 7;                                \
            cpa16(sA + swzoff(row, cv),                                           \
                  Ag + (size_t)row * (KTOT * 2) + kb + cv * 16);                  \
        }                                                                         \
        _Pragma("unroll")                                                         \
        for (int j = 0; j < 8; j++) {                                             \
            int idx = tid + j * GTHR;                                             \
            uint32_t row = idx >> 3, cv = idx & 7;                                \
            cpa16(sBs + swzoff(row, cv),                                          \
                  Bg + (size_t)row * (KTOT * 2) + kb + cv * 16);                  \
        }                                                                         \
    } while (0)

    FILL(0, 0);
    asm volatile("cp.async.commit_group;" ::: "memory");
    FILL(1, 1);
    asm volatile("cp.async.commit_group;" ::: "memory");

    int stg = 0;
    for (int i = 0; i < KITERS; i++) {
        asm volatile("cp.async.wait_group 1;" ::: "memory");
        __syncthreads();

        // prefetch stage i+2 (into buffer just freed by compute(i-1))
        if (i + 2 < KITERS) {
            int ns = stg + 2;
            if (ns >= STAGES) ns -= STAGES;
            FILL(i + 2, ns);
        }
        asm volatile("cp.async.commit_group;" ::: "memory");

        const uint32_t sA = sb + stg * STAGE_BYTES;
        const uint32_t sBs = sA + A_BYTES;

        #pragma unroll
        for (int k16 = 0; k16 < 4; k16++) {
            const uint32_t kc = k16 * 2;
            uint32_t a[4][4], br[4][4];
            #pragma unroll
            for (int mi = 0; mi < 4; mi++) {
                uint32_t row = wm * 64 + mi * 16 + (lane & 15);
                uint32_t chunk = kc + (lane >> 4);
                ldm4(sA + swzoff(row, chunk), a[mi][0], a[mi][1], a[mi][2], a[mi][3]);
            }
            #pragma unroll
            for (int njp = 0; njp < 4; njp++) {
                uint32_t row = wn * 64 + njp * 16 + ((lane >> 4) << 3) + (lane & 7);
                uint32_t chunk = kc + ((lane >> 3) & 1);
                ldm4(sBs + swzoff(row, chunk), br[njp][0], br[njp][1], br[njp][2], br[njp][3]);
            }
            #pragma unroll
            for (int mi = 0; mi < 4; mi++)
                #pragma unroll
                for (int nj = 0; nj < 8; nj++)
                    hmma(acc[mi][nj], a[mi], &br[nj >> 1][(nj & 1) * 2]);
        }
        stg = (stg + 1 == STAGES) ? 0 : stg + 1;
    }

    // ---------------- fused epilogue ----------------
    const float nst = nzs[0];
    const float gain = 1.4142135623730951f;
    const int r0 = lane >> 2;
    const int cpair = (lane & 3) * 2;

    float nzv[8][2];
    #pragma unroll
    for (int nj = 0; nj < 8; nj++) {
        int p = pbase + wn * 64 + nj * 8 + cpair;
        nzv[nj][0] = nzc[p] * nst;
        nzv[nj][1] = nzc[p + 1] * nst;
    }

    #pragma unroll
    for (int mi = 0; mi < 4; mi++) {
        #pragma unroll
        for (int h = 0; h < 2; h++) {
            int o = obase + wm * 64 + mi * 16 + h * 8 + r0;
            float dc = g_dcoef[b * 512 + o];
            float bias = cb[o];
            float* orow = out + (size_t)(b * 512 + o) * HW;
            #pragma unroll
            for (int nj = 0; nj < 8; nj++) {
                int p = pbase + wn * 64 + nj * 8 + cpair;
                float z0 = fmaf(acc[mi][nj][2 * h],     dc, nzv[nj][0] + bias);
                float z1 = fmaf(acc[mi][nj][2 * h + 1], dc, nzv[nj][1] + bias);
                float2 v;
                v.x = (z0 > 0.f ? z0 : 0.2f * z0) * gain;
                v.y = (z1 > 0.f ? z1 : 0.2f * z1) * gain;
                *(float2*)(orow + p) = v;
            }
        }
    }
}

// ---------------- ToRGB ----------------
__global__ void k_rgb(const float* __restrict__ x, const float* __restrict__ rgbw,
                      const float* __restrict__ rgbb, float* __restrict__ img) {
    __shared__ float rw[3][512];
    int b = blockIdx.y;
    int px = blockIdx.x * 256 + threadIdx.x;
    for (int i = threadIdx.x; i < 1536; i += 256) {
        int ch = i >> 9, o = i & 511;
        rw[ch][o] = rgbw[ch * 512 + o] * g_s2[b * 512 + o];
    }
    __syncthreads();
    const float* xp = x + (size_t)b * CH * HW + px;
    float a0 = 0.f, a1 = 0.f, a2 = 0.f;
    #pragma unroll 8
    for (int o = 0; o < 512; o++) {
        float xv = xp[(size_t)o * HW];
        a0 = fmaf(rw[0][o], xv, a0);
        a1 = fmaf(rw[1][o], xv, a1);
        a2 = fmaf(rw[2][o], xv, a2);
    }
    size_t base = (size_t)b * 3 * HW + px;
    img[base] = a0 + rgbb[0];
    img[base + HW] = a1 + rgbb[1];
    img[base + 2 * HW] = a2 + rgbb[2];
}

extern "C" void kernel_launch(void* const* d_in, const int* in_sizes, int n_in,
                              void* d_out, int out_size) {
    const float* ws   = (const float*)d_in[0];
    const float* cst  = (const float*)d_in[1];
    const float* cw   = (const float*)d_in[2];
    const float* cb   = (const float*)d_in[3];
    const float* caw  = (const float*)d_in[4];
    const float* cab  = (const float*)d_in[5];
    const float* nzc  = (const float*)d_in[6];
    const float* nzs  = (const float*)d_in[7];
    const float* rgbw = (const float*)d_in[8];
    const float* rgbb = (const float*)d_in[9];
    const float* raw  = (const float*)d_in[10];
    const float* rab  = (const float*)d_in[11];
    float* out = (float*)d_out;

    cudaFuncSetAttribute(k_gemm, cudaFuncAttributeMaxDynamicSharedMemorySize, SMEM_GEMM);

    k_style<<<1024, 256>>>(ws, caw, cab, raw, rab);
    k_wsq<<<1024, 256>>>(cw);
    k_dcoef<<<1024, 256>>>();
    k_aprep<<<BATCH * CH * KTOT / 8 / 256, 256>>>(cw);
    k_bprep<<<HW * KTOT / 4 / 256, 256>>>(cst);

    dim3 g(HW / 256, CH / 128, BATCH);   // (16, 4, 16) = 1024 CTAs
    k_gemm<<<g, GTHR, SMEM_GEMM>>>(nzc, nzs, cb, out);

    k_rgb<<<dim3(16, 16), 256>>>(out, rgbw, rgbb, out + (size_t)BATCH * CH * HW);
}

// round 8
// speedup vs baseline: 2.3014x; 1.0053x over previous
#include <cuda_runtime.h>
#include <cuda_fp16.h>
#include <math.h>
#include <stdint.h>

#define BATCH 16
#define CH 512
#define HW 4096
#define KTOT 4608           // 512 c * 9 taps
#define KITERS 72           // 4608 / 64
#define GTHR 256
#define STAGES 4
#define A_BYTES 16384       // 128 x 64 fp16
#define B_BYTES 32768       // 256 x 64 fp16
#define STAGE_BYTES (A_BYTES + B_BYTES)
#define SMEM_GEMM (STAGES * STAGE_BYTES)   // 192KB

// ---------------- scratch ----------------
__device__ float g_s[BATCH * CH];
__device__ float g_s2[BATCH * CH];
__device__ float g_dcoef[BATCH * CH];
__device__ float g_wsq[CH * CH];
__device__ __half g_A[BATCH * CH * KTOT];   // modulated weights [b][o][ck]
__device__ __half g_B[HW * KTOT];           // im2col patches  [p][ck]

__device__ __forceinline__ uint32_t s2u(const void* p) {
    return (uint32_t)__cvta_generic_to_shared(p);
}
__device__ __forceinline__ uint32_t swzoff(uint32_t row, uint32_t chunk) {
    return row * 128u + ((chunk ^ (row & 7u)) << 4);
}
__device__ __forceinline__ void cpa16(uint32_t s, const void* g) {
    asm volatile("cp.async.cg.shared.global [%0], [%1], 16;" :: "r"(s), "l"(g));
}
__device__ __forceinline__ void ldm4(uint32_t addr, uint32_t& r0, uint32_t& r1,
                                     uint32_t& r2, uint32_t& r3) {
    asm volatile("ldmatrix.sync.aligned.m8n8.x4.shared.b16 {%0,%1,%2,%3}, [%4];"
                 : "=r"(r0), "=r"(r1), "=r"(r2), "=r"(r3) : "r"(addr));
}
__device__ __forceinline__ void hmma(float* d, const uint32_t* a, const uint32_t* bf) {
    asm volatile(
        "mma.sync.aligned.m16n8k16.row.col.f32.f16.f16.f32 "
        "{%0,%1,%2,%3}, {%4,%5,%6,%7}, {%8,%9}, {%0,%1,%2,%3};"
        : "+f"(d[0]), "+f"(d[1]), "+f"(d[2]), "+f"(d[3])
        : "r"(a[0]), "r"(a[1]), "r"(a[2]), "r"(a[3]), "r"(bf[0]), "r"(bf[1]));
}

// ---------------- prep0: styles (blocks 0..1023) + wsq (blocks 1024..2047) ----------------
__global__ void k_prep0(const float* __restrict__ ws, const float* __restrict__ caw,
                        const float* __restrict__ cab, const float* __restrict__ raw,
                        const float* __restrict__ rab, const float* __restrict__ cw) {
    if (blockIdx.x < 1024) {
        int widx = blockIdx.x * 8 + (threadIdx.x >> 5);
        int lane = threadIdx.x & 31;
        int b = widx >> 9, c = widx & 511;
        const float* w0 = ws + b * 1024;
        const float* w1 = w0 + 512;
        const float* ca = caw + c * 512;
        const float* ra = raw + c * 512;
        float a1 = 0.f, a2 = 0.f;
        for (int d = lane; d < 512; d += 32) {
            a1 = fmaf(w0[d], ca[d], a1);
            a2 = fmaf(w1[d], ra[d], a2);
        }
        #pragma unroll
        for (int o = 16; o; o >>= 1) {
            a1 += __shfl_xor_sync(0xffffffffu, a1, o);
            a2 += __shfl_xor_sync(0xffffffffu, a2, o);
        }
        if (lane == 0) {
            g_s[b * 512 + c] = a1 + cab[c];
            g_s2[b * 512 + c] = (a2 + rab[c]) * 0.04419417382415922f;
        }
    } else {
        int idx = (blockIdx.x - 1024) * 256 + threadIdx.x;
        const float* p = cw + (size_t)idx * 9;
        float s = 0.f;
        #pragma unroll
        for (int k = 0; k < 9; k++) s = fmaf(p[k], p[k], s);
        g_wsq[idx] = s;
    }
}

// ---------------- dcoef ----------------
__global__ void k_dcoef() {
    int widx = blockIdx.x * 8 + (threadIdx.x >> 5);
    int lane = threadIdx.x & 31;
    int b = widx >> 9, o = widx & 511;
    const float* wq = g_wsq + o * 512;
    const float* sp = g_s + b * 512;
    float a = 0.f;
    for (int c = lane; c < 512; c += 32) {
        float sv = sp[c];
        a = fmaf(wq[c] * sv, sv, a);
    }
    #pragma unroll
    for (int off = 16; off; off >>= 1) a += __shfl_xor_sync(0xffffffffu, a, off);
    if (!lane) g_dcoef[b * 512 + o] = rsqrtf(a + 1e-8f);
}

// ---------------- prep1: A prep (x8) blocks 0..18431; B prep (x4) blocks 18432.. ----------------
__global__ void k_prep1(const float* __restrict__ cw, const float* __restrict__ cst) {
    if (blockIdx.x < 18432) {
        int idx = blockIdx.x * 256 + threadIdx.x;
        int ck8 = (idx % (KTOT / 8)) * 8;
        int rem = idx / (KTOT / 8);
        int o = rem & 511;
        int b = rem >> 9;
        const float* sp = g_s + b * 512;
        const float* wp = cw + (size_t)o * KTOT + ck8;
        float4 f0 = *(const float4*)(wp);
        float4 f1 = *(const float4*)(wp + 4);
        __half h[8];
        #pragma unroll
        for (int j = 0; j < 8; j++) {
            int c = (unsigned)(ck8 + j) / 9u;
            float wv = (j < 4) ? ((const float*)&f0)[j] : ((const float*)&f1)[j - 4];
            h[j] = __float2half_rn(wv * sp[c]);
        }
        *(uint4*)(g_A + (size_t)idx * 8) = *(const uint4*)h;
    } else {
        int idx = (blockIdx.x - 18432) * 256 + threadIdx.x;
        int ck4 = (idx % (KTOT / 4)) * 4;
        int p = idx / (KTOT / 4);
        int py = p >> 6, px = p & 63;
        __half h[4];
        #pragma unroll
        for (int j = 0; j < 4; j++) {
            int ck = ck4 + j;
            int c = (unsigned)ck / 9u;
            int k = ck - c * 9;
            int ky = (unsigned)k / 3u;
            int kx = k - ky * 3;
            int yy = py + ky - 1;
            int xx = px + kx - 1;
            float v = 0.f;
            if ((unsigned)yy < 64u && (unsigned)xx < 64u)
                v = cst[c * 4096 + yy * 64 + xx];
            h[j] = __float2half_rn(v);
        }
        *(uint2*)(g_B + (size_t)idx * 4) = *(const uint2*)h;
    }
}

// ---------------- main GEMM: 4-stage pipeline, K-chunk 64 ----------------
__global__ __launch_bounds__(GTHR, 1)
void k_gemm(const float* __restrict__ nzc, const float* __restrict__ nzs,
            const float* __restrict__ cb, float* __restrict__ out) {
    extern __shared__ char smem[];
    const uint32_t sb = s2u(smem);

    const int tid = threadIdx.x;
    const int wid = tid >> 5;
    const int lane = tid & 31;
    const int wm = wid & 1;        // 2 m-bands of 64
    const int wn = wid >> 1;       // 4 n-bands of 64

    const int b = blockIdx.z;
    const int obase = blockIdx.y * 128;
    const int pbase = blockIdx.x * 256;

    const char* Ag = (const char*)(g_A + (size_t)(b * 512 + obase) * KTOT);
    const char* Bg = (const char*)(g_B + (size_t)pbase * KTOT);

    float acc[4][8][4];
    #pragma unroll
    for (int mi = 0; mi < 4; mi++)
        #pragma unroll
        for (int nj = 0; nj < 8; nj++)
            #pragma unroll
            for (int q = 0; q < 4; q++) acc[mi][nj][q] = 0.f;

    #define FILL(KI, STG) do {                                                    \
        size_t kb = (size_t)(KI) * 128;                                           \
        uint32_t sA = sb + (STG) * STAGE_BYTES;                                   \
        uint32_t sBs = sA + A_BYTES;                                              \
        _Pragma("unroll")                                                         \
        for (int j = 0; j < 4; j++) {                                             \
            int idx = tid + j * GTHR;                                             \
            uint32_t row = idx >> 3, cv = idx & 7;                                \
            cpa16(sA + swzoff(row, cv),                                           \
                  Ag + (size_t)row * (KTOT * 2) + kb + cv * 16);                  \
        }                                                                         \
        _Pragma("unroll")                                                         \
        for (int j = 0; j < 8; j++) {                                             \
            int idx = tid + j * GTHR;                                             \
            uint32_t row = idx >> 3, cv = idx & 7;                                \
            cpa16(sBs + swzoff(row, cv),                                          \
                  Bg + (size_t)row * (KTOT * 2) + kb + cv * 16);                  \
        }                                                                         \
        asm volatile("cp.async.commit_group;" ::: "memory");                      \
    } while (0)

    FILL(0, 0);
    FILL(1, 1);
    FILL(2, 2);

    int stg = 0;
    for (int i = 0; i < KITERS; i++) {
        asm volatile("cp.async.wait_group 2;" ::: "memory");
        __syncthreads();

        if (i + 3 < KITERS) {
            int ns = stg + 3;
            if (ns >= STAGES) ns -= STAGES;
            FILL(i + 3, ns);
        } else {
            asm volatile("cp.async.commit_group;" ::: "memory");
        }

        const uint32_t sA = sb + stg * STAGE_BYTES;
        const uint32_t sBs = sA + A_BYTES;

        #pragma unroll
        for (int k16 = 0; k16 < 4; k16++) {
            const uint32_t kc = k16 * 2;
            uint32_t a[4][4], br[4][4];
            #pragma unroll
            for (int mi = 0; mi < 4; mi++) {
                uint32_t row = wm * 64 + mi * 16 + (lane & 15);
                uint32_t chunk = kc + (lane >> 4);
                ldm4(sA + swzoff(row, chunk), a[mi][0], a[mi][1], a[mi][2], a[mi][3]);
            }
            #pragma unroll
            for (int njp = 0; njp < 4; njp++) {
                uint32_t row = wn * 64 + njp * 16 + ((lane >> 4) << 3) + (lane & 7);
                uint32_t chunk = kc + ((lane >> 3) & 1);
                ldm4(sBs + swzoff(row, chunk), br[njp][0], br[njp][1], br[njp][2], br[njp][3]);
            }
            #pragma unroll
            for (int mi = 0; mi < 4; mi++)
                #pragma unroll
                for (int nj = 0; nj < 8; nj++)
                    hmma(acc[mi][nj], a[mi], &br[nj >> 1][(nj & 1) * 2]);
        }
        stg = (stg + 1 == STAGES) ? 0 : stg + 1;
    }

    // ---------------- fused epilogue ----------------
    const float nst = nzs[0];
    const float gain = 1.4142135623730951f;
    const int r0 = lane >> 2;
    const int cpair = (lane & 3) * 2;

    float nzv[8][2];
    #pragma unroll
    for (int nj = 0; nj < 8; nj++) {
        int p = pbase + wn * 64 + nj * 8 + cpair;
        nzv[nj][0] = nzc[p] * nst;
        nzv[nj][1] = nzc[p + 1] * nst;
    }

    #pragma unroll
    for (int mi = 0; mi < 4; mi++) {
        #pragma unroll
        for (int h = 0; h < 2; h++) {
            int o = obase + wm * 64 + mi * 16 + h * 8 + r0;
            float dc = g_dcoef[b * 512 + o];
            float bias = cb[o];
            float* orow = out + (size_t)(b * 512 + o) * HW;
            #pragma unroll
            for (int nj = 0; nj < 8; nj++) {
                int p = pbase + wn * 64 + nj * 8 + cpair;
                float z0 = fmaf(acc[mi][nj][2 * h],     dc, nzv[nj][0] + bias);
                float z1 = fmaf(acc[mi][nj][2 * h + 1], dc, nzv[nj][1] + bias);
                float2 v;
                v.x = (z0 > 0.f ? z0 : 0.2f * z0) * gain;
                v.y = (z1 > 0.f ? z1 : 0.2f * z1) * gain;
                *(float2*)(orow + p) = v;
            }
        }
    }
}

// ---------------- ToRGB ----------------
__global__ void k_rgb(const float* __restrict__ x, const float* __restrict__ rgbw,
                      const float* __restrict__ rgbb, float* __restrict__ img) {
    __shared__ float rw[3][512];
    int b = blockIdx.y;
    int px = blockIdx.x * 256 + threadIdx.x;
    for (int i = threadIdx.x; i < 1536; i += 256) {
        int ch = i >> 9, o = i & 511;
        rw[ch][o] = rgbw[ch * 512 + o] * g_s2[b * 512 + o];
    }
    __syncthreads();
    const float* xp = x + (size_t)b * CH * HW + px;
    float a0 = 0.f, a1 = 0.f, a2 = 0.f;
    #pragma unroll 8
    for (int o = 0; o < 512; o++) {
        float xv = xp[(size_t)o * HW];
        a0 = fmaf(rw[0][o], xv, a0);
        a1 = fmaf(rw[1][o], xv, a1);
        a2 = fmaf(rw[2][o], xv, a2);
    }
    size_t base = (size_t)b * 3 * HW + px;
    img[base] = a0 + rgbb[0];
    img[base + HW] = a1 + rgbb[1];
    img[base + 2 * HW] = a2 + rgbb[2];
}

extern "C" void kernel_launch(void* const* d_in, const int* in_sizes, int n_in,
                              void* d_out, int out_size) {
    const float* ws   = (const float*)d_in[0];
    const float* cst  = (const float*)d_in[1];
    const float* cw   = (const float*)d_in[2];
    const float* cb   = (const float*)d_in[3];
    const float* caw  = (const float*)d_in[4];
    const float* cab  = (const float*)d_in[5];
    const float* nzc  = (const float*)d_in[6];
    const float* nzs  = (const float*)d_in[7];
    const float* rgbw = (const float*)d_in[8];
    const float* rgbb = (const float*)d_in[9];
    const float* raw  = (const float*)d_in[10];
    const float* rab  = (const float*)d_in[11];
    float* out = (float*)d_out;

    cudaFuncSetAttribute(k_gemm, cudaFuncAttributeMaxDynamicSharedMemorySize, SMEM_GEMM);

    k_prep0<<<2048, 256>>>(ws, caw, cab, raw, rab, cw);          // launch 0
    k_dcoef<<<1024, 256>>>();                                    // launch 1
    k_prep1<<<36864, 256>>>(cw, cst);                            // launch 2
    dim3 g(HW / 256, CH / 128, BATCH);
    k_gemm<<<g, GTHR, SMEM_GEMM>>>(nzc, nzs, cb, out);           // launch 3 (profiled)
    k_rgb<<<dim3(16, 16), 256>>>(out, rgbw, rgbb, out + (size_t)BATCH * CH * HW);
}

// round 9
// speedup vs baseline: 2.4531x; 1.0659x over previous
#include <cuda_runtime.h>
#include <cuda_fp16.h>
#include <math.h>
#include <stdint.h>

#define BATCH 16
#define CH 512
#define HW 4096
#define KTOT 4608           // 512 c * 9 taps
#define KITERS 72           // 4608 / 64
#define GTHR 256
#define STAGES 3
#define A_BYTES 16384       // 128 x 64 fp16
#define B_BYTES 16384       // 128 x 64 fp16
#define STAGE_BYTES (A_BYTES + B_BYTES)
#define SMEM_GEMM (STAGES * STAGE_BYTES)   // 96KB per CTA, 2 CTAs/SM

// ---------------- scratch ----------------
__device__ float g_s[BATCH * CH];
__device__ float g_s2[BATCH * CH];
__device__ float g_dcoef[BATCH * CH];
__device__ float g_wsq[CH * CH];
__device__ __half g_A[BATCH * CH * KTOT];   // modulated weights [b][o][ck]
__device__ __half g_B[HW * KTOT];           // im2col patches  [p][ck]

__device__ __forceinline__ uint32_t s2u(const void* p) {
    return (uint32_t)__cvta_generic_to_shared(p);
}
__device__ __forceinline__ uint32_t swzoff(uint32_t row, uint32_t chunk) {
    return row * 128u + ((chunk ^ (row & 7u)) << 4);
}
__device__ __forceinline__ void cpa16(uint32_t s, const void* g) {
    asm volatile("cp.async.cg.shared.global [%0], [%1], 16;" :: "r"(s), "l"(g));
}
__device__ __forceinline__ void ldm4(uint32_t addr, uint32_t& r0, uint32_t& r1,
                                     uint32_t& r2, uint32_t& r3) {
    asm volatile("ldmatrix.sync.aligned.m8n8.x4.shared.b16 {%0,%1,%2,%3}, [%4];"
                 : "=r"(r0), "=r"(r1), "=r"(r2), "=r"(r3) : "r"(addr));
}
__device__ __forceinline__ void hmma(float* d, const uint32_t* a, const uint32_t* bf) {
    asm volatile(
        "mma.sync.aligned.m16n8k16.row.col.f32.f16.f16.f32 "
        "{%0,%1,%2,%3}, {%4,%5,%6,%7}, {%8,%9}, {%0,%1,%2,%3};"
        : "+f"(d[0]), "+f"(d[1]), "+f"(d[2]), "+f"(d[3])
        : "r"(a[0]), "r"(a[1]), "r"(a[2]), "r"(a[3]), "r"(bf[0]), "r"(bf[1]));
}

// ---------------- prep0: styles + wsq ----------------
__global__ void k_prep0(const float* __restrict__ ws, const float* __restrict__ caw,
                        const float* __restrict__ cab, const float* __restrict__ raw,
                        const float* __restrict__ rab, const float* __restrict__ cw) {
    if (blockIdx.x < 1024) {
        int widx = blockIdx.x * 8 + (threadIdx.x >> 5);
        int lane = threadIdx.x & 31;
        int b = widx >> 9, c = widx & 511;
        const float* w0 = ws + b * 1024;
        const float* w1 = w0 + 512;
        const float* ca = caw + c * 512;
        const float* ra = raw + c * 512;
        float a1 = 0.f, a2 = 0.f;
        for (int d = lane; d < 512; d += 32) {
            a1 = fmaf(w0[d], ca[d], a1);
            a2 = fmaf(w1[d], ra[d], a2);
        }
        #pragma unroll
        for (int o = 16; o; o >>= 1) {
            a1 += __shfl_xor_sync(0xffffffffu, a1, o);
            a2 += __shfl_xor_sync(0xffffffffu, a2, o);
        }
        if (lane == 0) {
            g_s[b * 512 + c] = a1 + cab[c];
            g_s2[b * 512 + c] = (a2 + rab[c]) * 0.04419417382415922f;
        }
    } else {
        int idx = (blockIdx.x - 1024) * 256 + threadIdx.x;
        const float* p = cw + (size_t)idx * 9;
        float s = 0.f;
        #pragma unroll
        for (int k = 0; k < 9; k++) s = fmaf(p[k], p[k], s);
        g_wsq[idx] = s;
    }
}

// ---------------- dcoef ----------------
__global__ void k_dcoef() {
    int widx = blockIdx.x * 8 + (threadIdx.x >> 5);
    int lane = threadIdx.x & 31;
    int b = widx >> 9, o = widx & 511;
    const float* wq = g_wsq + o * 512;
    const float* sp = g_s + b * 512;
    float a = 0.f;
    for (int c = lane; c < 512; c += 32) {
        float sv = sp[c];
        a = fmaf(wq[c] * sv, sv, a);
    }
    #pragma unroll
    for (int off = 16; off; off >>= 1) a += __shfl_xor_sync(0xffffffffu, a, off);
    if (!lane) g_dcoef[b * 512 + o] = rsqrtf(a + 1e-8f);
}

// ---------------- prep1: A prep (x8) + B prep (x4) ----------------
__global__ void k_prep1(const float* __restrict__ cw, const float* __restrict__ cst) {
    if (blockIdx.x < 18432) {
        int idx = blockIdx.x * 256 + threadIdx.x;
        int ck8 = (idx % (KTOT / 8)) * 8;
        int rem = idx / (KTOT / 8);
        int o = rem & 511;
        int b = rem >> 9;
        const float* sp = g_s + b * 512;
        const float* wp = cw + (size_t)o * KTOT + ck8;
        float4 f0 = *(const float4*)(wp);
        float4 f1 = *(const float4*)(wp + 4);
        __half h[8];
        #pragma unroll
        for (int j = 0; j < 8; j++) {
            int c = (unsigned)(ck8 + j) / 9u;
            float wv = (j < 4) ? ((const float*)&f0)[j] : ((const float*)&f1)[j - 4];
            h[j] = __float2half_rn(wv * sp[c]);
        }
        *(uint4*)(g_A + (size_t)idx * 8) = *(const uint4*)h;
    } else {
        int idx = (blockIdx.x - 18432) * 256 + threadIdx.x;
        int ck4 = (idx % (KTOT / 4)) * 4;
        int p = idx / (KTOT / 4);
        int py = p >> 6, px = p & 63;
        __half h[4];
        #pragma unroll
        for (int j = 0; j < 4; j++) {
            int ck = ck4 + j;
            int c = (unsigned)ck / 9u;
            int k = ck - c * 9;
            int ky = (unsigned)k / 3u;
            int kx = k - ky * 3;
            int yy = py + ky - 1;
            int xx = px + kx - 1;
            float v = 0.f;
            if ((unsigned)yy < 64u && (unsigned)xx < 64u)
                v = cst[c * 4096 + yy * 64 + xx];
            h[j] = __float2half_rn(v);
        }
        *(uint2*)(g_B + (size_t)idx * 4) = *(const uint2*)h;
    }
}

// ---------------- main GEMM: CTA 128x128, warp tile 64x32, 2 CTAs/SM ----------------
__global__ __launch_bounds__(GTHR, 2)
void k_gemm(const float* __restrict__ nzc, const float* __restrict__ nzs,
            const float* __restrict__ cb, float* __restrict__ out) {
    extern __shared__ char smem[];
    const uint32_t sb = s2u(smem);

    const int tid = threadIdx.x;
    const int wid = tid >> 5;
    const int lane = tid & 31;
    const int wm = wid & 1;        // 2 m-bands of 64
    const int wn = wid >> 1;       // 4 n-bands of 32

    const int b = blockIdx.z;
    const int obase = blockIdx.y * 128;
    const int pbase = blockIdx.x * 128;

    const char* Ag = (const char*)(g_A + (size_t)(b * 512 + obase) * KTOT);
    const char* Bg = (const char*)(g_B + (size_t)pbase * KTOT);

    float acc[4][4][4];
    #pragma unroll
    for (int mi = 0; mi < 4; mi++)
        #pragma unroll
        for (int nj = 0; nj < 4; nj++)
            #pragma unroll
            for (int q = 0; q < 4; q++) acc[mi][nj][q] = 0.f;

    // fill one stage: A 1024 + B 1024 chunk-loads over 256 threads
    #define FILL(KI, STG) do {                                                    \
        size_t kb = (size_t)(KI) * 128;                                           \
        uint32_t sA = sb + (STG) * STAGE_BYTES;                                   \
        uint32_t sBs = sA + A_BYTES;                                              \
        _Pragma("unroll")                                                         \
        for (int j = 0; j < 4; j++) {                                             \
            int idx = tid + j * GTHR;                                             \
            uint32_t row = idx >> 3, cv = idx & 7;                                \
            cpa16(sA + swzoff(row, cv),                                           \
                  Ag + (size_t)row * (KTOT * 2) + kb + cv * 16);                  \
        }                                                                         \
        _Pragma("unroll")                                                         \
        for (int j = 0; j < 4; j++) {                                             \
            int idx = tid + j * GTHR;                                             \
            uint32_t row = idx >> 3, cv = idx & 7;                                \
            cpa16(sBs + swzoff(row, cv),                                          \
                  Bg + (size_t)row * (KTOT * 2) + kb + cv * 16);                  \
        }                                                                         \
        asm volatile("cp.async.commit_group;" ::: "memory");                      \
    } while (0)

    FILL(0, 0);
    FILL(1, 1);

    int stg = 0;
    for (int i = 0; i < KITERS; i++) {
        asm volatile("cp.async.wait_group 1;" ::: "memory");
        __syncthreads();

        if (i + 2 < KITERS) {
            int ns = stg + 2;
            if (ns >= STAGES) ns -= STAGES;
            FILL(i + 2, ns);
        } else {
            asm volatile("cp.async.commit_group;" ::: "memory");
        }

        const uint32_t sA = sb + stg * STAGE_BYTES;
        const uint32_t sBs = sA + A_BYTES;

        #pragma unroll
        for (int k16 = 0; k16 < 4; k16++) {
            const uint32_t kc = k16 * 2;
            uint32_t a[4][4], br[2][4];
            #pragma unroll
            for (int mi = 0; mi < 4; mi++) {
                uint32_t row = wm * 64 + mi * 16 + (lane & 15);
                uint32_t chunk = kc + (lane >> 4);
                ldm4(sA + swzoff(row, chunk), a[mi][0], a[mi][1], a[mi][2], a[mi][3]);
            }
            #pragma unroll
            for (int njp = 0; njp < 2; njp++) {
                uint32_t row = wn * 32 + njp * 16 + ((lane >> 4) << 3) + (lane & 7);
                uint32_t chunk = kc + ((lane >> 3) & 1);
                ldm4(sBs + swzoff(row, chunk), br[njp][0], br[njp][1], br[njp][2], br[njp][3]);
            }
            #pragma unroll
            for (int mi = 0; mi < 4; mi++)
                #pragma unroll
                for (int nj = 0; nj < 4; nj++)
                    hmma(acc[mi][nj], a[mi], &br[nj >> 1][(nj & 1) * 2]);
        }
        stg = (stg + 1 == STAGES) ? 0 : stg + 1;
    }

    // ---------------- fused epilogue ----------------
    const float nst = nzs[0];
    const float gain = 1.4142135623730951f;
    const int r0 = lane >> 2;
    const int cpair = (lane & 3) * 2;

    float nzv[4][2];
    #pragma unroll
    for (int nj = 0; nj < 4; nj++) {
        int p = pbase + wn * 32 + nj * 8 + cpair;
        nzv[nj][0] = nzc[p] * nst;
        nzv[nj][1] = nzc[p + 1] * nst;
    }

    #pragma unroll
    for (int mi = 0; mi < 4; mi++) {
        #pragma unroll
        for (int h = 0; h < 2; h++) {
            int o = obase + wm * 64 + mi * 16 + h * 8 + r0;
            float dc = g_dcoef[b * 512 + o];
            float bias = cb[o];
            float* orow = out + (size_t)(b * 512 + o) * HW;
            #pragma unroll
            for (int nj = 0; nj < 4; nj++) {
                int p = pbase + wn * 32 + nj * 8 + cpair;
                float z0 = fmaf(acc[mi][nj][2 * h],     dc, nzv[nj][0] + bias);
                float z1 = fmaf(acc[mi][nj][2 * h + 1], dc, nzv[nj][1] + bias);
                float2 v;
                v.x = (z0 > 0.f ? z0 : 0.2f * z0) * gain;
                v.y = (z1 > 0.f ? z1 : 0.2f * z1) * gain;
                *(float2*)(orow + p) = v;
            }
        }
    }
}

// ---------------- ToRGB ----------------
__global__ void k_rgb(const float* __restrict__ x, const float* __restrict__ rgbw,
                      const float* __restrict__ rgbb, float* __restrict__ img) {
    __shared__ float rw[3][512];
    int b = blockIdx.y;
    int px = blockIdx.x * 256 + threadIdx.x;
    for (int i = threadIdx.x; i < 1536; i += 256) {
        int ch = i >> 9, o = i & 511;
        rw[ch][o] = rgbw[ch * 512 + o] * g_s2[b * 512 + o];
    }
    __syncthreads();
    const float* xp = x + (size_t)b * CH * HW + px;
    float a0 = 0.f, a1 = 0.f, a2 = 0.f;
    #pragma unroll 8
    for (int o = 0; o < 512; o++) {
        float xv = xp[(size_t)o * HW];
        a0 = fmaf(rw[0][o], xv, a0);
        a1 = fmaf(rw[1][o], xv, a1);
        a2 = fmaf(rw[2][o], xv, a2);
    }
    size_t base = (size_t)b * 3 * HW + px;
    img[base] = a0 + rgbb[0];
    img[base + HW] = a1 + rgbb[1];
    img[base + 2 * HW] = a2 + rgbb[2];
}

extern "C" void kernel_launch(void* const* d_in, const int* in_sizes, int n_in,
                              void* d_out, int out_size) {
    const float* ws   = (const float*)d_in[0];
    const float* cst  = (const float*)d_in[1];
    const float* cw   = (const float*)d_in[2];
    const float* cb   = (const float*)d_in[3];
    const float* caw  = (const float*)d_in[4];
    const float* cab  = (const float*)d_in[5];
    const float* nzc  = (const float*)d_in[6];
    const float* nzs  = (const float*)d_in[7];
    const float* rgbw = (const float*)d_in[8];
    const float* rgbb = (const float*)d_in[9];
    const float* raw  = (const float*)d_in[10];
    const float* rab  = (const float*)d_in[11];
    float* out = (float*)d_out;

    cudaFuncSetAttribute(k_gemm, cudaFuncAttributeMaxDynamicSharedMemorySize, SMEM_GEMM);

    k_prep0<<<2048, 256>>>(ws, caw, cab, raw, rab, cw);          // launch 0
    k_dcoef<<<1024, 256>>>();                                    // launch 1
    k_prep1<<<36864, 256>>>(cw, cst);                            // launch 2
    dim3 g(HW / 128, CH / 128, BATCH);                           // (32, 4, 16)
    k_gemm<<<g, GTHR, SMEM_GEMM>>>(nzc, nzs, cb, out);           // launch 3 (profiled)
    k_rgb<<<dim3(16, 16), 256>>>(out, rgbw, rgbb, out + (size_t)BATCH * CH * HW);
}